// round 7
// baseline (speedup 1.0000x reference)
#include <cuda_runtime.h>

// ---------------------------------------------------------------------------
// GTN forward, round 5.
//   k_pre  : blocks [0,256): XW = X @ Wg (32x64 tiles, coalesced As loads)
//            blocks [256,264): zero g_nnz + softmax edge weights
//   k_scan : streaming sparsify of A — 16 independent __ldcs loads/thread
//   k_y    : Y[c] = A2[c] @ XW (unroll-8 sparse gather)
//   k_final: dense smem H row (warp scatter w/ prefetched nnz), threshold,
//            out = relu(coef * (A1 . Y - dropped corrections) + bg)
// ---------------------------------------------------------------------------

#define NN 2048
#define NE 4
#define NC 2
#define WIN 512
#define WOUT 256
#define CAP 128
#define MAXDROP 128
#define THRESH 0.05f
#define WEPS 1e-4f

#define PLANE4 ((size_t)NN * NN / 4)    // float4 per plane = 1048576
#define QUART4 (PLANE4 / 4)             // 262144
#define SCAN_BLOCKS 1024                // 1024*256 = QUART4 threads
#define GEMM_BLOCKS 256                 // (2048/32)*(256/64)

// Scratch (device globals; no allocations allowed)
__device__ float4 g_f1v[NC];            // softmaxed edge weights, channel-major
__device__ float4 g_f2v[NC];
__device__ int    g_nnz[NN];
__device__ int    g_cols[NN * CAP];
__device__ float2 g_a1[NN * CAP];       // (.x,.y) = channel 0,1
__device__ float2 g_a2[NN * CAP];
__device__ float  g_XW[NN * WOUT];
__device__ float  g_Y[NC][NN * WOUT];

// ---------------------------------------------------------------- k_pre
__global__ void __launch_bounds__(256) k_pre(const float* __restrict__ X,
                                             const float* __restrict__ Wg,
                                             const float* __restrict__ W1a,
                                             const float* __restrict__ W1b) {
    __shared__ float As[16][33];        // padded: conflict-free transposed store
    __shared__ float Bs[16][64];
    const int tid = threadIdx.x;

    if (blockIdx.x >= GEMM_BLOCKS) {
        // ---------------------------------- init role: zero nnz + softmax
        int t = (blockIdx.x - GEMM_BLOCKS) * 256 + tid;
        if (t < NN) g_nnz[t] = 0;
        if (blockIdx.x == GEMM_BLOCKS && tid == 0) {
            for (int c = 0; c < NC; c++) {
                float m = -1e30f;
                for (int e = 0; e < NE; e++) m = fmaxf(m, W1a[c * NE + e]);
                float ex[NE], s = 0.f;
                for (int e = 0; e < NE; e++) { ex[e] = expf(W1a[c * NE + e] - m); s += ex[e]; }
                float f[NE];
                for (int e = 0; e < NE; e++) {
                    float w = ex[e] / s;
                    f[e] = (w < WEPS) ? 0.f : w;
                }
                g_f1v[c] = make_float4(f[0], f[1], f[2], f[3]);

                m = -1e30f;
                for (int e = 0; e < NE; e++) m = fmaxf(m, W1b[c * NE + e]);
                s = 0.f;
                for (int e = 0; e < NE; e++) { ex[e] = expf(W1b[c * NE + e] - m); s += ex[e]; }
                for (int e = 0; e < NE; e++) {
                    float w = ex[e] / s;
                    f[e] = (w < WEPS) ? 0.f : w;
                }
                g_f2v[c] = make_float4(f[0], f[1], f[2], f[3]);
            }
        }
        return;
    }

    // -------------------------------------- GEMM role: XW = X @ Wg
    const int b  = blockIdx.x;
    const int bm = (b >> 2) * 32;
    const int bn = (b & 3) * 64;
    const int tx = tid & 15;            // n / 4
    const int ty = tid >> 4;            // 0..15, 2 m-rows each
    float acc[2][4] = {};

    for (int k0 = 0; k0 < WIN; k0 += 16) {
        // As: consecutive tid -> consecutive k (coalesced 64B per 16 thr)
        #pragma unroll
        for (int t = 0; t < 2; t++) {
            int idx = tid + t * 256;
            int kk = idx & 15, m = idx >> 4;
            As[kk][m] = X[(size_t)(bm + m) * WIN + k0 + kk];
        }
        // Bs: consecutive tid -> consecutive n (coalesced)
        #pragma unroll
        for (int t = 0; t < 4; t++) {
            int idx = tid + t * 256;
            int n = idx & 63, kk = idx >> 6;
            Bs[kk][n] = Wg[(size_t)(k0 + kk) * WOUT + bn + n];
        }
        __syncthreads();
        #pragma unroll
        for (int k = 0; k < 16; k++) {
            float a0 = As[k][ty * 2 + 0];
            float a1 = As[k][ty * 2 + 1];
            float4 b4 = *(const float4*)&Bs[k][tx * 4];
            acc[0][0] = fmaf(a0, b4.x, acc[0][0]);
            acc[0][1] = fmaf(a0, b4.y, acc[0][1]);
            acc[0][2] = fmaf(a0, b4.z, acc[0][2]);
            acc[0][3] = fmaf(a0, b4.w, acc[0][3]);
            acc[1][0] = fmaf(a1, b4.x, acc[1][0]);
            acc[1][1] = fmaf(a1, b4.y, acc[1][1]);
            acc[1][2] = fmaf(a1, b4.z, acc[1][2]);
            acc[1][3] = fmaf(a1, b4.w, acc[1][3]);
        }
        __syncthreads();
    }
    #pragma unroll
    for (int u = 0; u < 2; u++) {
        float4 o = make_float4(acc[u][0], acc[u][1], acc[u][2], acc[u][3]);
        *(float4*)&g_XW[(size_t)(bm + ty * 2 + u) * WOUT + bn + tx * 4] = o;
    }
}

// ---------------------------------------------------------------- k_scan
__device__ __forceinline__ void scan_emit(int i, int j,
                                          float a0, float a1, float a2, float a3,
                                          const float4& f1a, const float4& f1b,
                                          const float4& f2a, const float4& f2b) {
    bool nz = (a0 != 0.f) | (a1 != 0.f) | (a2 != 0.f) | (a3 != 0.f);
    if (nz) {
        int slot = atomicAdd(&g_nnz[i], 1);
        if (slot < CAP) {
            int idx = i * CAP + slot;
            g_cols[idx] = j;
            g_a1[idx] = make_float2(
                f1a.x * a0 + f1a.y * a1 + f1a.z * a2 + f1a.w * a3,
                f1b.x * a0 + f1b.y * a1 + f1b.z * a2 + f1b.w * a3);
            g_a2[idx] = make_float2(
                f2a.x * a0 + f2a.y * a1 + f2a.z * a2 + f2a.w * a3,
                f2b.x * a0 + f2b.y * a1 + f2b.z * a2 + f2b.w * a3);
        }
    }
}

__device__ __forceinline__ void scan_quad(size_t p,
                                          const float4& v0, const float4& v1,
                                          const float4& v2, const float4& v3,
                                          const float4& f1a, const float4& f1b,
                                          const float4& f2a, const float4& f2b) {
    // fast path: all 16 values zero (common case ~83%)
    if ((v0.x == 0.f) & (v0.y == 0.f) & (v0.z == 0.f) & (v0.w == 0.f) &
        (v1.x == 0.f) & (v1.y == 0.f) & (v1.z == 0.f) & (v1.w == 0.f) &
        (v2.x == 0.f) & (v2.y == 0.f) & (v2.z == 0.f) & (v2.w == 0.f) &
        (v3.x == 0.f) & (v3.y == 0.f) & (v3.z == 0.f) & (v3.w == 0.f))
        return;
    int i = (int)(p >> 9);              // 512 float4 per row
    int j0 = ((int)p & 511) * 4;
    scan_emit(i, j0 + 0, v0.x, v1.x, v2.x, v3.x, f1a, f1b, f2a, f2b);
    scan_emit(i, j0 + 1, v0.y, v1.y, v2.y, v3.y, f1a, f1b, f2a, f2b);
    scan_emit(i, j0 + 2, v0.z, v1.z, v2.z, v3.z, f1a, f1b, f2a, f2b);
    scan_emit(i, j0 + 3, v0.w, v1.w, v2.w, v3.w, f1a, f1b, f2a, f2b);
}

__global__ void __launch_bounds__(256) k_scan(const float* __restrict__ A) {
    const size_t t = (size_t)blockIdx.x * 256 + threadIdx.x;   // 0..QUART4-1
    const float4* base = (const float4*)A;

    const float4 f1a = g_f1v[0], f1b = g_f1v[1];
    const float4 f2a = g_f2v[0], f2b = g_f2v[1];

    // 16 fully independent streaming loads in one batch
    float4 v[4][4];
    #pragma unroll
    for (int q = 0; q < 4; q++) {
        size_t p = t + (size_t)q * QUART4;
        #pragma unroll
        for (int e = 0; e < 4; e++)
            v[q][e] = __ldcs(base + p + (size_t)e * PLANE4);
    }
    #pragma unroll
    for (int q = 0; q < 4; q++)
        scan_quad(t + (size_t)q * QUART4, v[q][0], v[q][1], v[q][2], v[q][3],
                  f1a, f1b, f2a, f2b);
}

// ---------------------------------------------------------------- k_y
__global__ void __launch_bounds__(256) k_y() {
    const int k = blockIdx.x;
    const int f = threadIdx.x;
    __shared__ int   scol[CAP];
    __shared__ float sv0[CAP], sv1[CAP];
    const int n2 = min(g_nnz[k], CAP);
    for (int s = f; s < n2; s += 256) {
        int idx = k * CAP + s;
        scol[s] = g_cols[idx] * WOUT;
        float2 a = g_a2[idx];
        sv0[s] = a.x;
        sv1[s] = a.y;
    }
    __syncthreads();
    float acc0 = 0.f, acc1 = 0.f;
    int s = 0;
    for (; s + 8 <= n2; s += 8) {
        float x[8];
        #pragma unroll
        for (int u = 0; u < 8; u++) x[u] = __ldg(&g_XW[scol[s + u] + f]);
        #pragma unroll
        for (int u = 0; u < 8; u++) {
            acc0 = fmaf(sv0[s + u], x[u], acc0);
            acc1 = fmaf(sv1[s + u], x[u], acc1);
        }
    }
    for (; s + 4 <= n2; s += 4) {
        float x[4];
        #pragma unroll
        for (int u = 0; u < 4; u++) x[u] = __ldg(&g_XW[scol[s + u] + f]);
        #pragma unroll
        for (int u = 0; u < 4; u++) {
            acc0 = fmaf(sv0[s + u], x[u], acc0);
            acc1 = fmaf(sv1[s + u], x[u], acc1);
        }
    }
    for (; s < n2; s++) {
        float x = __ldg(&g_XW[scol[s] + f]);
        acc0 = fmaf(sv0[s], x, acc0);
        acc1 = fmaf(sv1[s], x, acc1);
    }
    g_Y[0][(size_t)k * WOUT + f] = acc0;
    g_Y[1][(size_t)k * WOUT + f] = acc1;
}

// ---------------------------------------------------------------- k_final
__global__ void __launch_bounds__(256) k_final(const float* __restrict__ bg,
                                               float* __restrict__ out) {
    const int i = blockIdx.x;
    const int tid = threadIdx.x;
    const int warp = tid >> 5, lane = tid & 31;

    __shared__ float H0[NN], H1[NN];
    __shared__ int   offs[CAP];          // c1*WOUT
    __shared__ int   n2s[CAP];           // prefetched neighbor nnz
    __shared__ float w0s[CAP], w1s[CAP];
    __shared__ float degsh[NC];
    __shared__ int   dropn[NC];
    __shared__ int   dropj[NC][MAXDROP];
    __shared__ float droph[NC][MAXDROP];

    float4 z = make_float4(0.f, 0.f, 0.f, 0.f);
    for (int t = tid; t < NN / 4; t += 256) {
        ((float4*)H0)[t] = z;
        ((float4*)H1)[t] = z;
    }
    if (tid < NC) { degsh[tid] = 0.f; dropn[tid] = 0; }
    const int n1 = min(g_nnz[i], CAP);
    for (int s = tid; s < n1; s += 256) {
        int idx = i * CAP + s;
        int c = g_cols[idx];
        offs[s] = c * WOUT;
        n2s[s] = min(g_nnz[c], CAP);
        float2 a = g_a1[idx];
        w0s[s] = a.x;
        w1s[s] = a.y;
    }
    __syncthreads();

    // scatter: one warp per source slot s, lanes over target slots s2
    for (int s = warp; s < n1; s += 8) {
        int kbase = (offs[s] / WOUT) * CAP;
        int n2 = n2s[s];
        float w0 = w0s[s], w1 = w1s[s];
        for (int s2 = lane; s2 < n2; s2 += 32) {
            int idx = kbase + s2;
            int j = g_cols[idx];
            float2 a = g_a2[idx];
            float h0 = w0 * a.x;
            float h1 = w1 * a.y;
            if (h0 != 0.f) atomicAdd(&H0[j], h0);
            if (h1 != 0.f) atomicAdd(&H1[j], h1);
        }
    }
    __syncthreads();

    // threshold scan: degree sums + dropped-entry lists
    float d0 = 0.f, d1 = 0.f;
    for (int j = tid; j < NN; j += 256) {
        float h0 = H0[j];
        if (h0 > THRESH) d0 += h0;
        else if (h0 > 0.f) {
            int p = atomicAdd(&dropn[0], 1);
            if (p < MAXDROP) { dropj[0][p] = j; droph[0][p] = h0; }
        }
        float h1 = H1[j];
        if (h1 > THRESH) d1 += h1;
        else if (h1 > 0.f) {
            int p = atomicAdd(&dropn[1], 1);
            if (p < MAXDROP) { dropj[1][p] = j; droph[1][p] = h1; }
        }
    }
    #pragma unroll
    for (int o = 16; o > 0; o >>= 1) {
        d0 += __shfl_down_sync(0xffffffff, d0, o);
        d1 += __shfl_down_sync(0xffffffff, d1, o);
    }
    if (lane == 0) {
        if (d0 != 0.f) atomicAdd(&degsh[0], d0);
        if (d1 != 0.f) atomicAdd(&degsh[1], d1);
    }
    __syncthreads();

    float coef[NC];
    #pragma unroll
    for (int c = 0; c < NC; c++) {
        float deg = degsh[c];
        if (deg > 0.f) {
            float dinv = 1.f / deg;
            float deg2 = deg * dinv;     // double row-normalization
            coef[c] = dinv * (1.f / deg2);
        } else {
            coef[c] = 0.f;
        }
    }

    // output: feature f = tid; interleave channel gathers (8 loads in flight)
    const int f = tid;
    const float bias = bg[f];
    const float* Y0 = g_Y[0];
    const float* Y1 = g_Y[1];
    float acc0 = 0.f, acc1 = 0.f;
    int s = 0;
    for (; s + 4 <= n1; s += 4) {
        int o0 = offs[s + 0] + f, o1 = offs[s + 1] + f;
        int o2 = offs[s + 2] + f, o3 = offs[s + 3] + f;
        float a0 = __ldg(Y0 + o0), b0 = __ldg(Y1 + o0);
        float a1 = __ldg(Y0 + o1), b1 = __ldg(Y1 + o1);
        float a2 = __ldg(Y0 + o2), b2 = __ldg(Y1 + o2);
        float a3 = __ldg(Y0 + o3), b3 = __ldg(Y1 + o3);
        acc0 = fmaf(w0s[s + 0], a0, acc0); acc1 = fmaf(w1s[s + 0], b0, acc1);
        acc0 = fmaf(w0s[s + 1], a1, acc0); acc1 = fmaf(w1s[s + 1], b1, acc1);
        acc0 = fmaf(w0s[s + 2], a2, acc0); acc1 = fmaf(w1s[s + 2], b2, acc1);
        acc0 = fmaf(w0s[s + 3], a3, acc0); acc1 = fmaf(w1s[s + 3], b3, acc1);
    }
    for (; s < n1; s++) {
        int o = offs[s] + f;
        acc0 = fmaf(w0s[s], __ldg(Y0 + o), acc0);
        acc1 = fmaf(w1s[s], __ldg(Y1 + o), acc1);
    }

    int nd0 = min(dropn[0], MAXDROP);
    for (int d = 0; d < nd0; d++)
        acc0 -= droph[0][d] * g_XW[(size_t)dropj[0][d] * WOUT + f];
    int nd1 = min(dropn[1], MAXDROP);
    for (int d = 0; d < nd1; d++)
        acc1 -= droph[1][d] * g_XW[(size_t)dropj[1][d] * WOUT + f];

    float o0 = coef[0] * acc0 + bias;
    float o1 = coef[1] * acc1 + bias;
    out[(size_t)i * (NC * WOUT) + f]        = fmaxf(o0, 0.f);
    out[(size_t)i * (NC * WOUT) + WOUT + f] = fmaxf(o1, 0.f);
}

// ---------------------------------------------------------------------------
extern "C" void kernel_launch(void* const* d_in, const int* in_sizes, int n_in,
                              void* d_out, int out_size) {
    const float* A   = (const float*)d_in[0];
    const float* X   = (const float*)d_in[1];
    const float* W1a = (const float*)d_in[2];
    const float* W1b = (const float*)d_in[3];
    const float* Wg  = (const float*)d_in[4];
    const float* bg  = (const float*)d_in[5];
    float* out = (float*)d_out;

    k_pre<<<GEMM_BLOCKS + 8, 256>>>(X, Wg, W1a, W1b);
    k_scan<<<SCAN_BLOCKS, 256>>>(A);
    k_y<<<NN, 256>>>();
    k_final<<<NN, 256>>>(bg, out);
}